// round 3
// baseline (speedup 1.0000x reference)
#include <cuda_runtime.h>
#include <cuda_bf16.h>
#include <cstdint>

typedef unsigned long long u64;

// Problem constants
#define NB 4
#define NS 2048
#define ND 1024
#define NH 16
#define NDK 64
#define NM (NB * NS)   // 8192 rows

// ---------------------------------------------------------------------------
// Scratch (device globals: allocation-free)
// ---------------------------------------------------------------------------
__device__ float g_Q[NB * NH * NS * NDK];   // [B,H,S,dk]
__device__ float g_K[NB * NH * NS * NDK];
__device__ float g_V[NB * NH * NS * NDK];
__device__ float g_AO[NB * NS * ND];        // attention output, [B,S,D]
__device__ __nv_bfloat16 g_Ahi[NM * ND];    // split activations
__device__ __nv_bfloat16 g_Alo[NM * ND];
__device__ __nv_bfloat16 g_Whi[ND * ND];    // split weights
__device__ __nv_bfloat16 g_Wlo[ND * ND];

// ---------------------------------------------------------------------------
// Helpers
// ---------------------------------------------------------------------------
__device__ __forceinline__ uint32_t smem_u32(const void* p) {
    uint32_t a;
    asm("{ .reg .u64 t; cvta.to.shared.u64 t, %1; cvt.u32.u64 %0, t; }" : "=r"(a) : "l"(p));
    return a;
}
#define SW128(bo) ((bo) ^ (((bo) >> 3) & 0x70))

__device__ __forceinline__ void ldm_x4(uint32_t& r0, uint32_t& r1, uint32_t& r2,
                                       uint32_t& r3, uint32_t addr) {
    asm volatile("ldmatrix.sync.aligned.m8n8.x4.shared.b16 {%0,%1,%2,%3}, [%4];"
                 : "=r"(r0), "=r"(r1), "=r"(r2), "=r"(r3) : "r"(addr));
}
__device__ __forceinline__ void mma16816(float* d, const uint32_t* a, const uint32_t* b) {
    asm volatile("mma.sync.aligned.m16n8k16.row.col.f32.bf16.bf16.f32 "
                 "{%0,%1,%2,%3}, {%4,%5,%6,%7}, {%8,%9}, {%0,%1,%2,%3};"
                 : "+f"(d[0]), "+f"(d[1]), "+f"(d[2]), "+f"(d[3])
                 : "r"(a[0]), "r"(a[1]), "r"(a[2]), "r"(a[3]), "r"(b[0]), "r"(b[1]));
}

// f32x2 packed ops
__device__ __forceinline__ u64 pk2(float lo, float hi) {
    u64 r; asm("mov.b64 %0, {%1, %2};" : "=l"(r) : "f"(lo), "f"(hi)); return r;
}
__device__ __forceinline__ void upk2(float& lo, float& hi, u64 v) {
    asm("mov.b64 {%0, %1}, %2;" : "=f"(lo), "=f"(hi) : "l"(v));
}
#define FFMA2(acc, a, b) asm("fma.rn.f32x2 %0, %1, %2, %0;" : "+l"(acc) : "l"(a), "l"(b))
#define FMUL2(acc, c)    asm("mul.rn.f32x2 %0, %0, %1;"     : "+l"(acc) : "l"(c))

// ---------------------------------------------------------------------------
// Split fp32 -> (bf16 hi, bf16 lo)
// ---------------------------------------------------------------------------
__global__ __launch_bounds__(256) void split_act(const float* __restrict__ src, int use_ao)
{
    const float* s = use_ao ? (const float*)g_AO : src;
    int i = (blockIdx.x * 256 + threadIdx.x) * 4;
    float4 v = *(const float4*)(s + i);
    float a[4] = {v.x, v.y, v.z, v.w};
    __nv_bfloat16 hi[4], lo[4];
#pragma unroll
    for (int t = 0; t < 4; t++) {
        hi[t] = __float2bfloat16(a[t]);
        lo[t] = __float2bfloat16(a[t] - __bfloat162float(hi[t]));
    }
    *(__nv_bfloat162*)(g_Ahi + i)     = __nv_bfloat162(hi[0], hi[1]);
    *(__nv_bfloat162*)(g_Ahi + i + 2) = __nv_bfloat162(hi[2], hi[3]);
    *(__nv_bfloat162*)(g_Alo + i)     = __nv_bfloat162(lo[0], lo[1]);
    *(__nv_bfloat162*)(g_Alo + i + 2) = __nv_bfloat162(lo[2], lo[3]);
}

__global__ __launch_bounds__(256) void split_wgt(const float* __restrict__ src)
{
    int i = (blockIdx.x * 256 + threadIdx.x) * 4;
    float4 v = *(const float4*)(src + i);
    float a[4] = {v.x, v.y, v.z, v.w};
    __nv_bfloat16 hi[4], lo[4];
#pragma unroll
    for (int t = 0; t < 4; t++) {
        hi[t] = __float2bfloat16(a[t]);
        lo[t] = __float2bfloat16(a[t] - __bfloat162float(hi[t]));
    }
    *(__nv_bfloat162*)(g_Whi + i)     = __nv_bfloat162(hi[0], hi[1]);
    *(__nv_bfloat162*)(g_Whi + i + 2) = __nv_bfloat162(hi[2], hi[3]);
    *(__nv_bfloat162*)(g_Wlo + i)     = __nv_bfloat162(lo[0], lo[1]);
    *(__nv_bfloat162*)(g_Wlo + i + 2) = __nv_bfloat162(lo[2], lo[3]);
}

// ---------------------------------------------------------------------------
// mma.sync GEMM: C[m,n] = sum_k A[m,k]*W[n,k] + bias[n], split bf16 (3 MMAs).
// 128x128 tile per CTA, K-chunk 64. 8 warps as 4(m) x 2(n): warp tile 32x64.
// Smem: Ahi/Alo/Whi/Wlo, each [128 rows][64 bf16] SW128-swizzled (16KB each).
// mode 0: C -> Cp row-major; mode 1/2/3: C -> g_Q/g_K/g_V heads layout.
// ---------------------------------------------------------------------------
#define GOFF_AHI 0
#define GOFF_ALO 16384
#define GOFF_WHI 32768
#define GOFF_WLO 49152
#define GEMM_SMEM 65536

__global__ __launch_bounds__(256) void gemm_tc(
    const float* __restrict__ bias, float* __restrict__ Cp, int mode)
{
    extern __shared__ __align__(1024) char smem[];
    const uint32_t sb = smem_u32(smem);
    const int tid = threadIdx.x;
    const int wid = tid >> 5;
    const int lane = tid & 31;
    const int wm = wid >> 1;        // 0..3
    const int wn = wid & 1;         // 0..1
    const int bm = blockIdx.y * 128;
    const int bn = blockIdx.x * 128;

    const __nv_bfloat16* srcs[4] = {g_Ahi, g_Alo, g_Whi, g_Wlo};
    const int row0[4] = {bm, bm, bn, bn};
    const uint32_t toff[4] = {GOFF_AHI, GOFF_ALO, GOFF_WHI, GOFF_WLO};

    float acc[2][8][4];
#pragma unroll
    for (int mi = 0; mi < 2; mi++)
#pragma unroll
        for (int nj = 0; nj < 8; nj++)
#pragma unroll
            for (int t = 0; t < 4; t++) acc[mi][nj][t] = 0.f;

    // ldmatrix lane-dependent address components
    const uint32_t aRow = (uint32_t)(wm * 32 + (lane & 15));         // + mi*16
    const uint32_t aKb  = (uint32_t)((lane >> 4) << 4);              // + ks*32
    const uint32_t bRow = (uint32_t)(wn * 64 + (lane & 7) + ((lane >> 4) & 1) * 8); // + nj*16
    const uint32_t bKb  = (uint32_t)(((lane >> 3) & 1) << 4);        // + ks*32

    for (int kc = 0; kc < 16; kc++) {
        const int k0 = kc * 64;
        if (kc > 0) __syncthreads();   // all warps done reading previous tiles
#pragma unroll
        for (int t = 0; t < 4; t++) {
#pragma unroll
            for (int u = 0; u < 4; u++) {
                int idx = u * 256 + tid;          // 0..1023
                int r = idx >> 3, c = idx & 7;
                uint32_t bo = (uint32_t)(r * 128 + c * 16);
                uint4 val = *(const uint4*)(srcs[t] + (row0[t] + r) * ND + k0 + c * 8);
                *(uint4*)(smem + toff[t] + SW128(bo)) = val;
            }
        }
        __syncthreads();

#pragma unroll
        for (int ks = 0; ks < 4; ks++) {
            uint32_t ah[2][4], al[2][4];
#pragma unroll
            for (int mi = 0; mi < 2; mi++) {
                uint32_t bo = (aRow + mi * 16) * 128 + (uint32_t)(ks * 32) + aKb;
                uint32_t off = SW128(bo);
                ldm_x4(ah[mi][0], ah[mi][1], ah[mi][2], ah[mi][3], sb + GOFF_AHI + off);
                ldm_x4(al[mi][0], al[mi][1], al[mi][2], al[mi][3], sb + GOFF_ALO + off);
            }
            uint32_t bh[4][4], bl[4][4];
#pragma unroll
            for (int nj = 0; nj < 4; nj++) {
                uint32_t bo = (bRow + nj * 16) * 128 + (uint32_t)(ks * 32) + bKb;
                uint32_t off = SW128(bo);
                ldm_x4(bh[nj][0], bh[nj][1], bh[nj][2], bh[nj][3], sb + GOFF_WHI + off);
                ldm_x4(bl[nj][0], bl[nj][1], bl[nj][2], bl[nj][3], sb + GOFF_WLO + off);
            }
#pragma unroll
            for (int mi = 0; mi < 2; mi++)
#pragma unroll
                for (int nj = 0; nj < 4; nj++) {
                    mma16816(acc[mi][nj * 2 + 0], ah[mi], &bh[nj][0]);
                    mma16816(acc[mi][nj * 2 + 0], ah[mi], &bl[nj][0]);
                    mma16816(acc[mi][nj * 2 + 0], al[mi], &bh[nj][0]);
                    mma16816(acc[mi][nj * 2 + 1], ah[mi], &bh[nj][2]);
                    mma16816(acc[mi][nj * 2 + 1], ah[mi], &bl[nj][2]);
                    mma16816(acc[mi][nj * 2 + 1], al[mi], &bh[nj][2]);
                }
        }
    }

    // Epilogue: thread (lane>>2)=row-in-16, (lane&3)=col-pair
    float* dstH = (mode == 1) ? (float*)g_Q : (mode == 2) ? (float*)g_K : (float*)g_V;
    const int g = lane >> 2, tg = lane & 3;
#pragma unroll
    for (int mi = 0; mi < 2; mi++) {
#pragma unroll
        for (int nj = 0; nj < 8; nj++) {
            int n = bn + wn * 64 + nj * 8 + tg * 2;
            float bx = bias[n], by = bias[n + 1];
            int m0 = bm + wm * 32 + mi * 16 + g;
#pragma unroll
            for (int half = 0; half < 2; half++) {
                int m = m0 + half * 8;
                float2 o = make_float2(acc[mi][nj][half * 2 + 0] + bx,
                                       acc[mi][nj][half * 2 + 1] + by);
                if (mode == 0) {
                    *(float2*)(Cp + (size_t)m * ND + n) = o;
                } else {
                    int bb = m >> 11, ss = m & 2047;
                    int h = n >> 6, dd = n & 63;
                    *(float2*)(dstH + (((bb * NH + h) * NS + ss) * NDK) + dd) = o;
                }
            }
        }
    }
}

// ---------------------------------------------------------------------------
// Flash attention, fp32 with packed f32x2 FMAs.
// One block = (b, h, 64-row q tile). 256 threads. Dynamic smem 96KB:
//   Qt   [64 d][64 r]      16KB — pairs along r are native u64
//   Kdup [64 d][128]       32KB — each K value duplicated {v,v}
//   Pt   [64 c][64 r]      16KB
//   Vdup [64 jj][128]      32KB — each V value duplicated {v,v}
// ---------------------------------------------------------------------------
#define FOFF_QT   0
#define FOFF_KDUP 16384
#define FOFF_PT   49152
#define FOFF_VDUP 65536
#define FLASH_SMEM 98304

__global__ __launch_bounds__(256) void flash_attn(const int* __restrict__ mask)
{
    extern __shared__ __align__(16) char fsm[];
    float* Qt = (float*)(fsm + FOFF_QT);
    float* Kd = (float*)(fsm + FOFF_KDUP);
    float* Pt = (float*)(fsm + FOFF_PT);
    float* Vd = (float*)(fsm + FOFF_VDUP);

    const int tid = threadIdx.x;
    const int qt = blockIdx.x;
    const int h  = blockIdx.y;
    const int b  = blockIdx.z;
    const int ty = tid >> 4;
    const int tx = tid & 15;

    const float* Qb = g_Q + ((b * NH + h) * NS + qt * 64) * NDK;
    const float* Kb = g_K + ((b * NH + h) * NS) * NDK;
    const float* Vb = g_V + ((b * NH + h) * NS) * NDK;

    // Load Q tile transposed: Qt[d][r]
#pragma unroll
    for (int u = 0; u < 4; u++) {
        int idx = tid + u * 256;
        int r = idx & 63;
        int q = idx >> 6;
        float4 a = *(const float4*)(Qb + r * NDK + q * 4);
        Qt[(q * 4 + 0) * 64 + r] = a.x;
        Qt[(q * 4 + 1) * 64 + r] = a.y;
        Qt[(q * 4 + 2) * 64 + r] = a.z;
        Qt[(q * 4 + 3) * 64 + r] = a.w;
    }

    const float NEG = __int_as_float(0xff800000);
    float m_i[4] = {NEG, NEG, NEG, NEG};
    float l_i[4] = {0.f, 0.f, 0.f, 0.f};
    u64 acc2[2][4] = {{0, 0, 0, 0}, {0, 0, 0, 0}};

    const int qg0 = qt * 64 + ty * 4;

    for (int kt = 0; kt < NS / 64; kt++) {
        // K tile transposed + duplicated: Kd[d][2c] = Kd[d][2c+1] = K[c][d]
#pragma unroll
        for (int u = 0; u < 4; u++) {
            int idx = tid + u * 256;
            int r = idx & 63;
            int q = idx >> 6;
            float4 k4 = *(const float4*)(Kb + (kt * 64 + r) * NDK + q * 4);
            *(float2*)&Kd[(q * 4 + 0) * 128 + r * 2] = make_float2(k4.x, k4.x);
            *(float2*)&Kd[(q * 4 + 1) * 128 + r * 2] = make_float2(k4.y, k4.y);
            *(float2*)&Kd[(q * 4 + 2) * 128 + r * 2] = make_float2(k4.z, k4.z);
            *(float2*)&Kd[(q * 4 + 3) * 128 + r * 2] = make_float2(k4.w, k4.w);
        }
        // V tile duplicated: Vd[jj][2d] = Vd[jj][2d+1] = V[jj][d]
#pragma unroll
        for (int u = 0; u < 4; u++) {
            int idx = tid + u * 256;
            int r = idx >> 4;
            int q = idx & 15;
            float4 v4 = *(const float4*)(Vb + (kt * 64 + r) * NDK + q * 4);
            *(float2*)&Vd[r * 128 + (q * 4 + 0) * 2] = make_float2(v4.x, v4.x);
            *(float2*)&Vd[r * 128 + (q * 4 + 1) * 2] = make_float2(v4.y, v4.y);
            *(float2*)&Vd[r * 128 + (q * 4 + 2) * 2] = make_float2(v4.z, v4.z);
            *(float2*)&Vd[r * 128 + (q * 4 + 3) * 2] = make_float2(v4.w, v4.w);
        }
        __syncthreads();

        // QK^T: s2[ip][j] = packed pair over i = {2ip, 2ip+1}
        u64 s2[2][4] = {{0, 0, 0, 0}, {0, 0, 0, 0}};
#pragma unroll 8
        for (int d = 0; d < 64; d++) {
            const u64* qa = (const u64*)&Qt[d * 64 + ty * 4];
            u64 a01 = qa[0], a23 = qa[1];
            const ulonglong2* bp = (const ulonglong2*)&Kd[d * 128 + tx * 8];
            ulonglong2 b01 = bp[0], b23 = bp[1];
            FFMA2(s2[0][0], a01, b01.x); FFMA2(s2[1][0], a23, b01.x);
            FFMA2(s2[0][1], a01, b01.y); FFMA2(s2[1][1], a23, b01.y);
            FFMA2(s2[0][2], a01, b23.x); FFMA2(s2[1][2], a23, b23.x);
            FFMA2(s2[0][3], a01, b23.y); FFMA2(s2[1][3], a23, b23.y);
        }
        float s[4][4];
#pragma unroll
        for (int j = 0; j < 4; j++) {
            upk2(s[0][j], s[1][j], s2[0][j]);
            upk2(s[2][j], s[3][j], s2[1][j]);
        }

        // mask + scale + online softmax
        const int kg0 = kt * 64 + tx * 4;
        float p[4][4], corr[4];
#pragma unroll
        for (int i = 0; i < 4; i++) {
            int4 mr = *(const int4*)(mask + (size_t)(qg0 + i) * NS + kg0);
            s[i][0] = mr.x ? s[i][0] * 0.125f : -1e9f;
            s[i][1] = mr.y ? s[i][1] * 0.125f : -1e9f;
            s[i][2] = mr.z ? s[i][2] * 0.125f : -1e9f;
            s[i][3] = mr.w ? s[i][3] * 0.125f : -1e9f;

            float r = fmaxf(fmaxf(s[i][0], s[i][1]), fmaxf(s[i][2], s[i][3]));
            r = fmaxf(r, __shfl_xor_sync(0xffffffffu, r, 1));
            r = fmaxf(r, __shfl_xor_sync(0xffffffffu, r, 2));
            r = fmaxf(r, __shfl_xor_sync(0xffffffffu, r, 4));
            r = fmaxf(r, __shfl_xor_sync(0xffffffffu, r, 8));
            float mn = fmaxf(m_i[i], r);
            corr[i] = __expf(m_i[i] - mn);

            float rs = 0.f;
#pragma unroll
            for (int j = 0; j < 4; j++) {
                p[i][j] = __expf(s[i][j] - mn);
                rs += p[i][j];
            }
            rs += __shfl_xor_sync(0xffffffffu, rs, 1);
            rs += __shfl_xor_sync(0xffffffffu, rs, 2);
            rs += __shfl_xor_sync(0xffffffffu, rs, 4);
            rs += __shfl_xor_sync(0xffffffffu, rs, 8);

            l_i[i] = l_i[i] * corr[i] + rs;
            m_i[i] = mn;
        }
        {
            u64 c01 = pk2(corr[0], corr[1]);
            u64 c23 = pk2(corr[2], corr[3]);
#pragma unroll
            for (int j = 0; j < 4; j++) { FMUL2(acc2[0][j], c01); FMUL2(acc2[1][j], c23); }
        }

        // store P transposed: Pt[c][r]
#pragma unroll
        for (int j = 0; j < 4; j++)
            *(float4*)&Pt[(tx * 4 + j) * 64 + ty * 4] =
                make_float4(p[0][j], p[1][j], p[2][j], p[3][j]);
        __syncthreads();

        // P@V: acc2[ip][jd] += Pt pairs * Vd broadcast
#pragma unroll 8
        for (int jj = 0; jj < 64; jj++) {
            const u64* pa = (const u64*)&Pt[jj * 64 + ty * 4];
            u64 p01 = pa[0], p23 = pa[1];
            const ulonglong2* vp = (const ulonglong2*)&Vd[jj * 128 + tx * 8];
            ulonglong2 v01 = vp[0], v23 = vp[1];
            FFMA2(acc2[0][0], p01, v01.x); FFMA2(acc2[1][0], p23, v01.x);
            FFMA2(acc2[0][1], p01, v01.y); FFMA2(acc2[1][1], p23, v01.y);
            FFMA2(acc2[0][2], p01, v23.x); FFMA2(acc2[1][2], p23, v23.x);
            FFMA2(acc2[0][3], p01, v23.y); FFMA2(acc2[1][3], p23, v23.y);
        }
        __syncthreads();  // before next tile overwrites Kd / Vd / Pt
    }

    // epilogue
    float acc[4][4];
#pragma unroll
    for (int j = 0; j < 4; j++) {
        upk2(acc[0][j], acc[1][j], acc2[0][j]);
        upk2(acc[2][j], acc[3][j], acc2[1][j]);
    }
    float* Ob = g_AO + (size_t)(b * NS) * ND + h * NDK;
#pragma unroll
    for (int i = 0; i < 4; i++) {
        float inv = 1.f / l_i[i];
        float4 o = make_float4(acc[i][0] * inv, acc[i][1] * inv,
                               acc[i][2] * inv, acc[i][3] * inv);
        *(float4*)(Ob + (size_t)(qg0 + i) * ND + tx * 4) = o;
    }
}

// ---------------------------------------------------------------------------
extern "C" void kernel_launch(void* const* d_in, const int* in_sizes, int n_in,
                              void* d_out, int out_size)
{
    const float* q    = (const float*)d_in[0];
    const float* k    = (const float*)d_in[1];
    const float* v    = (const float*)d_in[2];
    const int*   mask = (const int*)d_in[3];
    const float* w_q  = (const float*)d_in[4];
    const float* b_q  = (const float*)d_in[5];
    const float* w_k  = (const float*)d_in[6];
    const float* b_k  = (const float*)d_in[7];
    const float* w_v  = (const float*)d_in[8];
    const float* b_v  = (const float*)d_in[9];
    const float* w_o  = (const float*)d_in[10];
    const float* b_o  = (const float*)d_in[11];

    cudaFuncSetAttribute(gemm_tc, cudaFuncAttributeMaxDynamicSharedMemorySize, GEMM_SMEM);
    cudaFuncSetAttribute(flash_attn, cudaFuncAttributeMaxDynamicSharedMemorySize, FLASH_SMEM);

    const int actBlocks = NM * ND / (4 * 256);  // 8192
    const int wBlocks   = ND * ND / (4 * 256);  // 1024
    dim3 ggrid(ND / 128, NM / 128);             // (8, 64)

    // Q projection
    split_wgt<<<wBlocks, 256>>>(w_q);
    split_act<<<actBlocks, 256>>>(q, 0);
    gemm_tc<<<ggrid, 256, GEMM_SMEM>>>(b_q, nullptr, 1);
    // K projection
    split_wgt<<<wBlocks, 256>>>(w_k);
    split_act<<<actBlocks, 256>>>(k, 0);
    gemm_tc<<<ggrid, 256, GEMM_SMEM>>>(b_k, nullptr, 2);
    // V projection
    split_wgt<<<wBlocks, 256>>>(w_v);
    split_act<<<actBlocks, 256>>>(v, 0);
    gemm_tc<<<ggrid, 256, GEMM_SMEM>>>(b_v, nullptr, 3);

    // attention
    dim3 agrid(NS / 64, NH, NB);  // (32, 16, 4)
    flash_attn<<<agrid, 256, FLASH_SMEM>>>(mask);

    // output projection
    split_wgt<<<wBlocks, 256>>>(w_o);
    split_act<<<actBlocks, 256>>>(nullptr, 1);
    gemm_tc<<<ggrid, 256, GEMM_SMEM>>>(b_o, (float*)d_out, 0);
}

// round 4
// speedup vs baseline: 1.7991x; 1.7991x over previous
#include <cuda_runtime.h>
#include <cuda_bf16.h>
#include <cstdint>

typedef unsigned long long u64;

// Problem constants
#define NB 4
#define NS 2048
#define ND 1024
#define NH 16
#define NDK 64
#define NM (NB * NS)   // 8192 rows

// ---------------------------------------------------------------------------
// Scratch (device globals: allocation-free)
// ---------------------------------------------------------------------------
__device__ float g_Q[NB * NH * NS * NDK];   // [B,H,S,dk]
__device__ float g_K[NB * NH * NS * NDK];
__device__ float g_V[NB * NH * NS * NDK];
__device__ float g_AO[NB * NS * ND];        // attention output, [B,S,D]
__device__ __nv_bfloat16 g_Ahi[NM * ND];    // split activations
__device__ __nv_bfloat16 g_Alo[NM * ND];
__device__ __nv_bfloat16 g_Whi[ND * ND];    // split weights
__device__ __nv_bfloat16 g_Wlo[ND * ND];

// ---------------------------------------------------------------------------
// Helpers
// ---------------------------------------------------------------------------
__device__ __forceinline__ uint32_t smem_u32(const void* p) {
    uint32_t a;
    asm("{ .reg .u64 t; cvta.to.shared.u64 t, %1; cvt.u32.u64 %0, t; }" : "=r"(a) : "l"(p));
    return a;
}
#define SW128(bo) ((bo) ^ (((bo) >> 3) & 0x70))

__device__ __forceinline__ void ldm_x4(uint32_t& r0, uint32_t& r1, uint32_t& r2,
                                       uint32_t& r3, uint32_t addr) {
    asm volatile("ldmatrix.sync.aligned.m8n8.x4.shared.b16 {%0,%1,%2,%3}, [%4];"
                 : "=r"(r0), "=r"(r1), "=r"(r2), "=r"(r3) : "r"(addr));
}
__device__ __forceinline__ void mma16816(float* d, const uint32_t* a, const uint32_t* b) {
    asm volatile("mma.sync.aligned.m16n8k16.row.col.f32.bf16.bf16.f32 "
                 "{%0,%1,%2,%3}, {%4,%5,%6,%7}, {%8,%9}, {%0,%1,%2,%3};"
                 : "+f"(d[0]), "+f"(d[1]), "+f"(d[2]), "+f"(d[3])
                 : "r"(a[0]), "r"(a[1]), "r"(a[2]), "r"(a[3]), "r"(b[0]), "r"(b[1]));
}

__device__ __forceinline__ void cp_async16(uint32_t s, const void* g) {
    asm volatile("{ .reg .u64 gg; cvta.to.global.u64 gg, %1; "
                 "cp.async.cg.shared.global [%0], [gg], 16; }"
                 :: "r"(s), "l"(g) : "memory");
}
#define CP_COMMIT() asm volatile("cp.async.commit_group;" ::: "memory")
#define CP_WAIT1()  asm volatile("cp.async.wait_group 1;" ::: "memory")
#define CP_WAIT0()  asm volatile("cp.async.wait_group 0;" ::: "memory")

// f32x2 packed ops
__device__ __forceinline__ u64 pk2(float lo, float hi) {
    u64 r; asm("mov.b64 %0, {%1, %2};" : "=l"(r) : "f"(lo), "f"(hi)); return r;
}
__device__ __forceinline__ void upk2(float& lo, float& hi, u64 v) {
    asm("mov.b64 {%0, %1}, %2;" : "=f"(lo), "=f"(hi) : "l"(v));
}
#define FFMA2(acc, a, b) asm("fma.rn.f32x2 %0, %1, %2, %0;" : "+l"(acc) : "l"(a), "l"(b))
#define FMUL2(acc, c)    asm("mul.rn.f32x2 %0, %0, %1;"     : "+l"(acc) : "l"(c))

// ---------------------------------------------------------------------------
// Split fp32 -> (bf16 hi, bf16 lo)
// ---------------------------------------------------------------------------
__global__ __launch_bounds__(256) void split_act(const float* __restrict__ src, int use_ao)
{
    const float* s = use_ao ? (const float*)g_AO : src;
    int i = (blockIdx.x * 256 + threadIdx.x) * 4;
    float4 v = *(const float4*)(s + i);
    float a[4] = {v.x, v.y, v.z, v.w};
    __nv_bfloat16 hi[4], lo[4];
#pragma unroll
    for (int t = 0; t < 4; t++) {
        hi[t] = __float2bfloat16(a[t]);
        lo[t] = __float2bfloat16(a[t] - __bfloat162float(hi[t]));
    }
    *(__nv_bfloat162*)(g_Ahi + i)     = __nv_bfloat162(hi[0], hi[1]);
    *(__nv_bfloat162*)(g_Ahi + i + 2) = __nv_bfloat162(hi[2], hi[3]);
    *(__nv_bfloat162*)(g_Alo + i)     = __nv_bfloat162(lo[0], lo[1]);
    *(__nv_bfloat162*)(g_Alo + i + 2) = __nv_bfloat162(lo[2], lo[3]);
}

__global__ __launch_bounds__(256) void split_wgt(const float* __restrict__ src)
{
    int i = (blockIdx.x * 256 + threadIdx.x) * 4;
    float4 v = *(const float4*)(src + i);
    float a[4] = {v.x, v.y, v.z, v.w};
    __nv_bfloat16 hi[4], lo[4];
#pragma unroll
    for (int t = 0; t < 4; t++) {
        hi[t] = __float2bfloat16(a[t]);
        lo[t] = __float2bfloat16(a[t] - __bfloat162float(hi[t]));
    }
    *(__nv_bfloat162*)(g_Whi + i)     = __nv_bfloat162(hi[0], hi[1]);
    *(__nv_bfloat162*)(g_Whi + i + 2) = __nv_bfloat162(hi[2], hi[3]);
    *(__nv_bfloat162*)(g_Wlo + i)     = __nv_bfloat162(lo[0], lo[1]);
    *(__nv_bfloat162*)(g_Wlo + i + 2) = __nv_bfloat162(lo[2], lo[3]);
}

// ---------------------------------------------------------------------------
// mma.sync GEMM, 2-stage cp.async pipeline.
// C[m,n] = sum_k A[m,k]*W[n,k] + bias[n], split bf16 (3 MMAs per combo).
// 128x128 tile per CTA, K-chunk 64. 8 warps as 4(m) x 2(n): warp tile 32x64.
// Smem: 2 stages x 4 tiles (Ahi/Alo/Whi/Wlo), each [128][64] bf16 SW128 (16KB).
// ---------------------------------------------------------------------------
#define GOFF_AHI 0
#define GOFF_ALO 16384
#define GOFF_WHI 32768
#define GOFF_WLO 49152
#define GSTAGE   65536
#define GEMM_SMEM (2 * GSTAGE)

__global__ __launch_bounds__(256) void gemm_tc(
    const float* __restrict__ bias, float* __restrict__ Cp, int mode)
{
    extern __shared__ __align__(1024) char smem[];
    const uint32_t sb = smem_u32(smem);
    const int tid = threadIdx.x;
    const int wid = tid >> 5;
    const int lane = tid & 31;
    const int wm = wid >> 1;        // 0..3
    const int wn = wid & 1;         // 0..1
    const int bm = blockIdx.y * 128;
    const int bn = blockIdx.x * 128;

    const __nv_bfloat16* srcs[4] = {g_Ahi, g_Alo, g_Whi, g_Wlo};
    const int row0[4] = {bm, bm, bn, bn};
    const uint32_t toff[4] = {GOFF_AHI, GOFF_ALO, GOFF_WHI, GOFF_WLO};

    float acc[2][8][4];
#pragma unroll
    for (int mi = 0; mi < 2; mi++)
#pragma unroll
        for (int nj = 0; nj < 8; nj++)
#pragma unroll
            for (int t = 0; t < 4; t++) acc[mi][nj][t] = 0.f;

    // ldmatrix lane-dependent address components
    const uint32_t aRow = (uint32_t)(wm * 32 + (lane & 15));
    const uint32_t aKb  = (uint32_t)((lane >> 4) << 4);
    const uint32_t bRow = (uint32_t)(wn * 64 + (lane & 7) + ((lane >> 4) & 1) * 8);
    const uint32_t bKb  = (uint32_t)(((lane >> 3) & 1) << 4);

    // stage loader: global -> smem via cp.async
    auto load_stage = [&](int kc) {
        const int k0 = kc * 64;
        const uint32_t sbase = sb + (uint32_t)((kc & 1) * GSTAGE);
#pragma unroll
        for (int t = 0; t < 4; t++) {
#pragma unroll
            for (int u = 0; u < 4; u++) {
                int idx = u * 256 + tid;          // 0..1023
                int r = idx >> 3, c = idx & 7;
                uint32_t bo = (uint32_t)(r * 128 + c * 16);
                cp_async16(sbase + toff[t] + SW128(bo),
                           srcs[t] + (size_t)(row0[t] + r) * ND + k0 + c * 8);
            }
        }
    };

    load_stage(0);
    CP_COMMIT();

    for (int kc = 0; kc < 16; kc++) {
        if (kc < 15) {
            load_stage(kc + 1);
            CP_COMMIT();
            CP_WAIT1();      // stage kc complete, kc+1 in flight
        } else {
            CP_WAIT0();
        }
        __syncthreads();

        const uint32_t stage = sb + (uint32_t)((kc & 1) * GSTAGE);
#pragma unroll
        for (int ks = 0; ks < 4; ks++) {
            uint32_t ah[2][4], al[2][4];
#pragma unroll
            for (int mi = 0; mi < 2; mi++) {
                uint32_t bo = (aRow + mi * 16) * 128 + (uint32_t)(ks * 32) + aKb;
                uint32_t off = SW128(bo);
                ldm_x4(ah[mi][0], ah[mi][1], ah[mi][2], ah[mi][3], stage + GOFF_AHI + off);
                ldm_x4(al[mi][0], al[mi][1], al[mi][2], al[mi][3], stage + GOFF_ALO + off);
            }
            uint32_t bh[4][4], bl[4][4];
#pragma unroll
            for (int nj = 0; nj < 4; nj++) {
                uint32_t bo = (bRow + nj * 16) * 128 + (uint32_t)(ks * 32) + bKb;
                uint32_t off = SW128(bo);
                ldm_x4(bh[nj][0], bh[nj][1], bh[nj][2], bh[nj][3], stage + GOFF_WHI + off);
                ldm_x4(bl[nj][0], bl[nj][1], bl[nj][2], bl[nj][3], stage + GOFF_WLO + off);
            }
#pragma unroll
            for (int mi = 0; mi < 2; mi++)
#pragma unroll
                for (int nj = 0; nj < 4; nj++) {
                    mma16816(acc[mi][nj * 2 + 0], ah[mi], &bh[nj][0]);
                    mma16816(acc[mi][nj * 2 + 0], ah[mi], &bl[nj][0]);
                    mma16816(acc[mi][nj * 2 + 0], al[mi], &bh[nj][0]);
                    mma16816(acc[mi][nj * 2 + 1], ah[mi], &bh[nj][2]);
                    mma16816(acc[mi][nj * 2 + 1], ah[mi], &bl[nj][2]);
                    mma16816(acc[mi][nj * 2 + 1], al[mi], &bh[nj][2]);
                }
        }
        __syncthreads();   // all warps done with this stage before it is reloaded
    }

    // Epilogue
    float* dstH = (mode == 1) ? (float*)g_Q : (mode == 2) ? (float*)g_K : (float*)g_V;
    const int g = lane >> 2, tg = lane & 3;
#pragma unroll
    for (int mi = 0; mi < 2; mi++) {
#pragma unroll
        for (int nj = 0; nj < 8; nj++) {
            int n = bn + wn * 64 + nj * 8 + tg * 2;
            float bx = bias[n], by = bias[n + 1];
            int m0 = bm + wm * 32 + mi * 16 + g;
#pragma unroll
            for (int half = 0; half < 2; half++) {
                int m = m0 + half * 8;
                float2 o = make_float2(acc[mi][nj][half * 2 + 0] + bx,
                                       acc[mi][nj][half * 2 + 1] + by);
                if (mode == 0) {
                    *(float2*)(Cp + (size_t)m * ND + n) = o;
                } else {
                    int bb = m >> 11, ss = m & 2047;
                    int h = n >> 6, dd = n & 63;
                    *(float2*)(dstH + (((bb * NH + h) * NS + ss) * NDK) + dd) = o;
                }
            }
        }
    }
}

// ---------------------------------------------------------------------------
// Flash attention, fp32 with packed f32x2 FMAs, pairs packed along the
// OUTPUT/j axis so the streamed operand (K, V) is a native contiguous pair
// (dense conflict-free loads) and the duplicated operand (Q, P) is indexed
// only by ty -> warp-broadcast smem reads (no conflicts).
// One block = (b, h, 64-row q tile). 256 threads (16 ty x 16 tx).
// Smem (dynamic, 99,328 B -> 2 CTAs/SM):
//   Qd [64 d][128]      32KB  dup pairs {q,q}, read addr depends on ty only
//   Kt [64 d][64 c]     16KB  K transposed, read as float4 by tx (dense)
//   Vs [64 j][64 d]     16KB  V direct, read as float4 by tx (dense)
//   Pd [64 j][132]      33KB  dup P transposed (132-word stride vs conflicts)
// ---------------------------------------------------------------------------
#define FQD 0
#define FKT 32768
#define FVS 49152
#define FPD 65536
#define FLASH_SMEM (65536 + 64 * 132 * 4)   // 99328

__global__ __launch_bounds__(256) void flash_attn(const int* __restrict__ mask)
{
    extern __shared__ __align__(16) char fsm[];
    float* Qd = (float*)(fsm + FQD);
    float* Kt = (float*)(fsm + FKT);
    float* Vs = (float*)(fsm + FVS);
    float* Pd = (float*)(fsm + FPD);

    const int tid = threadIdx.x;
    const int qt = blockIdx.x;
    const int h  = blockIdx.y;
    const int b  = blockIdx.z;
    const int ty = tid >> 4;
    const int tx = tid & 15;

    const float* Qb = g_Q + ((size_t)(b * NH + h) * NS + qt * 64) * NDK;
    const float* Kb = g_K + (size_t)(b * NH + h) * NS * NDK;
    const float* Vb = g_V + (size_t)(b * NH + h) * NS * NDK;

    // Qd fill: Qd[d][2r] = Qd[d][2r+1] = Q[r][d]
#pragma unroll
    for (int u = 0; u < 4; u++) {
        int idx = tid + u * 256;
        int r = idx & 63;
        int q = idx >> 6;
        float4 a = *(const float4*)(Qb + r * NDK + q * 4);
        *(float2*)&Qd[(q * 4 + 0) * 128 + 2 * r] = make_float2(a.x, a.x);
        *(float2*)&Qd[(q * 4 + 1) * 128 + 2 * r] = make_float2(a.y, a.y);
        *(float2*)&Qd[(q * 4 + 2) * 128 + 2 * r] = make_float2(a.z, a.z);
        *(float2*)&Qd[(q * 4 + 3) * 128 + 2 * r] = make_float2(a.w, a.w);
    }

    const float NEG = __int_as_float(0xff800000);
    float m_i[4] = {NEG, NEG, NEG, NEG};
    float l_i[4] = {0.f, 0.f, 0.f, 0.f};
    u64 acc2[4][2] = {{0,0},{0,0},{0,0},{0,0}};   // acc2[i][jp]: out pair {jd,jd+1}

    const int qg0 = qt * 64 + ty * 4;

    for (int kt = 0; kt < NS / 64; kt++) {
        // Kt fill (transposed, scalar stores, dense banks)
#pragma unroll
        for (int u = 0; u < 4; u++) {
            int idx = tid + u * 256;
            int r = idx & 63;
            int q = idx >> 6;
            float4 k4 = *(const float4*)(Kb + (size_t)(kt * 64 + r) * NDK + q * 4);
            Kt[(q * 4 + 0) * 64 + r] = k4.x;
            Kt[(q * 4 + 1) * 64 + r] = k4.y;
            Kt[(q * 4 + 2) * 64 + r] = k4.z;
            Kt[(q * 4 + 3) * 64 + r] = k4.w;
        }
        // Vs fill (direct copy)
#pragma unroll
        for (int u = 0; u < 4; u++) {
            int idx = tid + u * 256;
            int r = idx >> 4;
            int q = idx & 15;
            *(float4*)&Vs[r * 64 + q * 4] =
                *(const float4*)(Vb + (size_t)(kt * 64 + r) * NDK + q * 4);
        }
        __syncthreads();

        // QK^T: s2[i][jp] packed over j. K pairs native, Q dup broadcast.
        u64 s2[4][2] = {{0,0},{0,0},{0,0},{0,0}};
#pragma unroll 8
        for (int d = 0; d < 64; d++) {
            ulonglong2 qA = *(const ulonglong2*)&Qd[d * 128 + ty * 8];
            ulonglong2 qB = *(const ulonglong2*)&Qd[d * 128 + ty * 8 + 4];
            const u64* kk = (const u64*)&Kt[d * 64 + tx * 4];
            u64 k01 = kk[0], k23 = kk[1];
            FFMA2(s2[0][0], k01, qA.x); FFMA2(s2[0][1], k23, qA.x);
            FFMA2(s2[1][0], k01, qA.y); FFMA2(s2[1][1], k23, qA.y);
            FFMA2(s2[2][0], k01, qB.x); FFMA2(s2[2][1], k23, qB.x);
            FFMA2(s2[3][0], k01, qB.y); FFMA2(s2[3][1], k23, qB.y);
        }
        float s[4][4];
#pragma unroll
        for (int i = 0; i < 4; i++) {
            upk2(s[i][0], s[i][1], s2[i][0]);
            upk2(s[i][2], s[i][3], s2[i][1]);
        }

        // mask + scale + online softmax
        const int kg0 = kt * 64 + tx * 4;
        float p[4][4], corr[4];
#pragma unroll
        for (int i = 0; i < 4; i++) {
            int4 mr = *(const int4*)(mask + (size_t)(qg0 + i) * NS + kg0);
            s[i][0] = mr.x ? s[i][0] * 0.125f : -1e9f;
            s[i][1] = mr.y ? s[i][1] * 0.125f : -1e9f;
            s[i][2] = mr.z ? s[i][2] * 0.125f : -1e9f;
            s[i][3] = mr.w ? s[i][3] * 0.125f : -1e9f;

            float r = fmaxf(fmaxf(s[i][0], s[i][1]), fmaxf(s[i][2], s[i][3]));
            r = fmaxf(r, __shfl_xor_sync(0xffffffffu, r, 1));
            r = fmaxf(r, __shfl_xor_sync(0xffffffffu, r, 2));
            r = fmaxf(r, __shfl_xor_sync(0xffffffffu, r, 4));
            r = fmaxf(r, __shfl_xor_sync(0xffffffffu, r, 8));
            float mn = fmaxf(m_i[i], r);
            corr[i] = __expf(m_i[i] - mn);

            float rs = 0.f;
#pragma unroll
            for (int j = 0; j < 4; j++) {
                p[i][j] = __expf(s[i][j] - mn);
                rs += p[i][j];
            }
            rs += __shfl_xor_sync(0xffffffffu, rs, 1);
            rs += __shfl_xor_sync(0xffffffffu, rs, 2);
            rs += __shfl_xor_sync(0xffffffffu, rs, 4);
            rs += __shfl_xor_sync(0xffffffffu, rs, 8);

            l_i[i] = l_i[i] * corr[i] + rs;
            m_i[i] = mn;
        }
#pragma unroll
        for (int i = 0; i < 4; i++) {
            u64 cc = pk2(corr[i], corr[i]);
            FMUL2(acc2[i][0], cc);
            FMUL2(acc2[i][1], cc);
        }

        // store P transposed + duplicated: Pd[c][2r] = Pd[c][2r+1] = P[r][c]
#pragma unroll
        for (int j = 0; j < 4; j++) {
            int base = (tx * 4 + j) * 132 + ty * 8;
            *(float4*)&Pd[base]     = make_float4(p[0][j], p[0][j], p[1][j], p[1][j]);
            *(float4*)&Pd[base + 4] = make_float4(p[2][j], p[2][j], p[3][j], p[3][j]);
        }
        __syncthreads();

        // P@V: acc2[i][jp] += V pairs (native) * P dup (broadcast)
#pragma unroll 8
        for (int jj = 0; jj < 64; jj++) {
            ulonglong2 pA = *(const ulonglong2*)&Pd[jj * 132 + ty * 8];
            ulonglong2 pB = *(const ulonglong2*)&Pd[jj * 132 + ty * 8 + 4];
            const u64* vv = (const u64*)&Vs[jj * 64 + tx * 4];
            u64 v01 = vv[0], v23 = vv[1];
            FFMA2(acc2[0][0], v01, pA.x); FFMA2(acc2[0][1], v23, pA.x);
            FFMA2(acc2[1][0], v01, pA.y); FFMA2(acc2[1][1], v23, pA.y);
            FFMA2(acc2[2][0], v01, pB.x); FFMA2(acc2[2][1], v23, pB.x);
            FFMA2(acc2[3][0], v01, pB.y); FFMA2(acc2[3][1], v23, pB.y);
        }
        __syncthreads();   // before next tile overwrites Kt / Vs / Pd
    }

    // epilogue
    float* Ob = g_AO + (size_t)(b * NS) * ND + h * NDK;
#pragma unroll
    for (int i = 0; i < 4; i++) {
        float inv = 1.f / l_i[i];
        float a0, a1, a2, a3;
        upk2(a0, a1, acc2[i][0]);
        upk2(a2, a3, acc2[i][1]);
        float4 o = make_float4(a0 * inv, a1 * inv, a2 * inv, a3 * inv);
        *(float4*)(Ob + (size_t)(qg0 + i) * ND + tx * 4) = o;
    }
}

// ---------------------------------------------------------------------------
extern "C" void kernel_launch(void* const* d_in, const int* in_sizes, int n_in,
                              void* d_out, int out_size)
{
    const float* q    = (const float*)d_in[0];
    const float* k    = (const float*)d_in[1];
    const float* v    = (const float*)d_in[2];
    const int*   mask = (const int*)d_in[3];
    const float* w_q  = (const float*)d_in[4];
    const float* b_q  = (const float*)d_in[5];
    const float* w_k  = (const float*)d_in[6];
    const float* b_k  = (const float*)d_in[7];
    const float* w_v  = (const float*)d_in[8];
    const float* b_v  = (const float*)d_in[9];
    const float* w_o  = (const float*)d_in[10];
    const float* b_o  = (const float*)d_in[11];

    cudaFuncSetAttribute(gemm_tc, cudaFuncAttributeMaxDynamicSharedMemorySize, GEMM_SMEM);
    cudaFuncSetAttribute(flash_attn, cudaFuncAttributeMaxDynamicSharedMemorySize, FLASH_SMEM);

    const int actBlocks = NM * ND / (4 * 256);  // 8192
    const int wBlocks   = ND * ND / (4 * 256);  // 1024
    dim3 ggrid(ND / 128, NM / 128);             // (8, 64)

    // Q projection
    split_wgt<<<wBlocks, 256>>>(w_q);
    split_act<<<actBlocks, 256>>>(q, 0);
    gemm_tc<<<ggrid, 256, GEMM_SMEM>>>(b_q, nullptr, 1);
    // K projection
    split_wgt<<<wBlocks, 256>>>(w_k);
    split_act<<<actBlocks, 256>>>(k, 0);
    gemm_tc<<<ggrid, 256, GEMM_SMEM>>>(b_k, nullptr, 2);
    // V projection
    split_wgt<<<wBlocks, 256>>>(w_v);
    split_act<<<actBlocks, 256>>>(v, 0);
    gemm_tc<<<ggrid, 256, GEMM_SMEM>>>(b_v, nullptr, 3);

    // attention
    dim3 agrid(NS / 64, NH, NB);  // (32, 16, 4)
    flash_attn<<<agrid, 256, FLASH_SMEM>>>(mask);

    // output projection
    split_wgt<<<wBlocks, 256>>>(w_o);
    split_act<<<actBlocks, 256>>>(nullptr, 1);
    gemm_tc<<<ggrid, 256, GEMM_SMEM>>>(b_o, (float*)d_out, 0);
}

// round 5
// speedup vs baseline: 4.5223x; 2.5137x over previous
#include <cuda_runtime.h>
#include <cuda_bf16.h>
#include <cstdint>

typedef unsigned long long u64;

// Problem constants
#define NB 4
#define NS 2048
#define ND 1024
#define NH 16
#define NDK 64
#define NM (NB * NS)   // 8192 rows

// ---------------------------------------------------------------------------
// Scratch (device globals: allocation-free)
// ---------------------------------------------------------------------------
__device__ __align__(16) __nv_bfloat16 g_Ahi[NM * ND];    // split activations / attn out
__device__ __align__(16) __nv_bfloat16 g_Alo[NM * ND];
__device__ __align__(16) __nv_bfloat16 g_Whi[ND * ND];    // split weights
__device__ __align__(16) __nv_bfloat16 g_Wlo[ND * ND];
__device__ __align__(16) __nv_bfloat16 g_Qhi[NB * NH * NS * NDK];  // [B,H,S,dk]
__device__ __align__(16) __nv_bfloat16 g_Qlo[NB * NH * NS * NDK];
__device__ __align__(16) __nv_bfloat16 g_Khi[NB * NH * NS * NDK];
__device__ __align__(16) __nv_bfloat16 g_Klo[NB * NH * NS * NDK];
__device__ __align__(16) __nv_bfloat16 g_Vhi[NB * NH * NS * NDK];
__device__ __align__(16) __nv_bfloat16 g_Vlo[NB * NH * NS * NDK];
__device__ __align__(16) u64 g_maskbits[NS * NS / 64];    // bit-packed mask

// ---------------------------------------------------------------------------
// Helpers
// ---------------------------------------------------------------------------
__device__ __forceinline__ uint32_t smem_u32(const void* p) {
    uint32_t a;
    asm("{ .reg .u64 t; cvta.to.shared.u64 t, %1; cvt.u32.u64 %0, t; }" : "=r"(a) : "l"(p));
    return a;
}
#define SW128(bo) ((bo) ^ (((bo) >> 3) & 0x70))

__device__ __forceinline__ void ldm_x4(uint32_t& r0, uint32_t& r1, uint32_t& r2,
                                       uint32_t& r3, uint32_t addr) {
    asm volatile("ldmatrix.sync.aligned.m8n8.x4.shared.b16 {%0,%1,%2,%3}, [%4];"
                 : "=r"(r0), "=r"(r1), "=r"(r2), "=r"(r3) : "r"(addr));
}
__device__ __forceinline__ void ldm_x4t(uint32_t& r0, uint32_t& r1, uint32_t& r2,
                                        uint32_t& r3, uint32_t addr) {
    asm volatile("ldmatrix.sync.aligned.m8n8.x4.trans.shared.b16 {%0,%1,%2,%3}, [%4];"
                 : "=r"(r0), "=r"(r1), "=r"(r2), "=r"(r3) : "r"(addr));
}
__device__ __forceinline__ void mma16816(float* d, const uint32_t* a, const uint32_t* b) {
    asm volatile("mma.sync.aligned.m16n8k16.row.col.f32.bf16.bf16.f32 "
                 "{%0,%1,%2,%3}, {%4,%5,%6,%7}, {%8,%9}, {%0,%1,%2,%3};"
                 : "+f"(d[0]), "+f"(d[1]), "+f"(d[2]), "+f"(d[3])
                 : "r"(a[0]), "r"(a[1]), "r"(a[2]), "r"(a[3]), "r"(b[0]), "r"(b[1]));
}

__device__ __forceinline__ void cp_async16(uint32_t s, const void* g) {
    asm volatile("{ .reg .u64 gg; cvta.to.global.u64 gg, %1; "
                 "cp.async.cg.shared.global [%0], [gg], 16; }"
                 :: "r"(s), "l"(g) : "memory");
}
#define CP_COMMIT() asm volatile("cp.async.commit_group;" ::: "memory")
#define CP_WAIT1()  asm volatile("cp.async.wait_group 1;" ::: "memory")
#define CP_WAIT0()  asm volatile("cp.async.wait_group 0;" ::: "memory")

// split fp32 pair -> packed bf16 hi pair + bf16 residual pair
__device__ __forceinline__ void split_pair(float a, float b, uint32_t& hi, uint32_t& lo) {
    __nv_bfloat16 ha = __float2bfloat16(a), hb = __float2bfloat16(b);
    __nv_bfloat16 la = __float2bfloat16(a - __bfloat162float(ha));
    __nv_bfloat16 lb = __float2bfloat16(b - __bfloat162float(hb));
    __nv_bfloat162 H(ha, hb), L(la, lb);
    hi = *reinterpret_cast<uint32_t*>(&H);
    lo = *reinterpret_cast<uint32_t*>(&L);
}

// ---------------------------------------------------------------------------
// Preprocess kernels
// ---------------------------------------------------------------------------
__global__ __launch_bounds__(256) void split_act(const float* __restrict__ src)
{
    int i = (blockIdx.x * 256 + threadIdx.x) * 4;
    float4 v = *(const float4*)(src + i);
    uint32_t h0, l0, h1, l1;
    split_pair(v.x, v.y, h0, l0);
    split_pair(v.z, v.w, h1, l1);
    *(uint32_t*)(g_Ahi + i) = h0; *(uint32_t*)(g_Ahi + i + 2) = h1;
    *(uint32_t*)(g_Alo + i) = l0; *(uint32_t*)(g_Alo + i + 2) = l1;
}

__global__ __launch_bounds__(256) void split_wgt(const float* __restrict__ src)
{
    int i = (blockIdx.x * 256 + threadIdx.x) * 4;
    float4 v = *(const float4*)(src + i);
    uint32_t h0, l0, h1, l1;
    split_pair(v.x, v.y, h0, l0);
    split_pair(v.z, v.w, h1, l1);
    *(uint32_t*)(g_Whi + i) = h0; *(uint32_t*)(g_Whi + i + 2) = h1;
    *(uint32_t*)(g_Wlo + i) = l0; *(uint32_t*)(g_Wlo + i + 2) = l1;
}

// mask int32[S][S] -> bitmap u64[S][S/64]
__global__ __launch_bounds__(256) void mask_pack(const int* __restrict__ mask)
{
    int w = blockIdx.x * 256 + threadIdx.x;     // 0 .. 65535
    const int4* src = (const int4*)(mask + (size_t)w * 64);
    u64 bits = 0;
#pragma unroll
    for (int q = 0; q < 16; q++) {
        int4 v = src[q];
        bits |= ((u64)(v.x != 0) << (q * 4 + 0)) | ((u64)(v.y != 0) << (q * 4 + 1))
              | ((u64)(v.z != 0) << (q * 4 + 2)) | ((u64)(v.w != 0) << (q * 4 + 3));
    }
    g_maskbits[w] = bits;
}

// ---------------------------------------------------------------------------
// mma.sync GEMM, 2-stage cp.async pipeline (proven R4).
// C[m,n] = sum_k A[m,k]*W[n,k] + bias[n], split bf16 (3 MMAs per combo).
// mode 0: fp32 -> Cp row-major.
// mode 1/2/3: split bf16 hi/lo -> g_Q / g_K / g_V heads layout [B,H,S,dk].
// ---------------------------------------------------------------------------
#define GOFF_AHI 0
#define GOFF_ALO 16384
#define GOFF_WHI 32768
#define GOFF_WLO 49152
#define GSTAGE   65536
#define GEMM_SMEM (2 * GSTAGE)

__global__ __launch_bounds__(256) void gemm_tc(
    const float* __restrict__ bias, float* __restrict__ Cp, int mode)
{
    extern __shared__ __align__(1024) char smem[];
    const uint32_t sb = smem_u32(smem);
    const int tid = threadIdx.x;
    const int wid = tid >> 5;
    const int lane = tid & 31;
    const int wm = wid >> 1;
    const int wn = wid & 1;
    const int bm = blockIdx.y * 128;
    const int bn = blockIdx.x * 128;

    const __nv_bfloat16* srcs[4] = {g_Ahi, g_Alo, g_Whi, g_Wlo};
    const int row0[4] = {bm, bm, bn, bn};
    const uint32_t toff[4] = {GOFF_AHI, GOFF_ALO, GOFF_WHI, GOFF_WLO};

    float acc[2][8][4];
#pragma unroll
    for (int mi = 0; mi < 2; mi++)
#pragma unroll
        for (int nj = 0; nj < 8; nj++)
#pragma unroll
            for (int t = 0; t < 4; t++) acc[mi][nj][t] = 0.f;

    const uint32_t aRow = (uint32_t)(wm * 32 + (lane & 15));
    const uint32_t aKb  = (uint32_t)((lane >> 4) << 4);
    const uint32_t bRow = (uint32_t)(wn * 64 + (lane & 7) + ((lane >> 4) & 1) * 8);
    const uint32_t bKb  = (uint32_t)(((lane >> 3) & 1) << 4);

    auto load_stage = [&](int kc) {
        const int k0 = kc * 64;
        const uint32_t sbase = sb + (uint32_t)((kc & 1) * GSTAGE);
#pragma unroll
        for (int t = 0; t < 4; t++) {
#pragma unroll
            for (int u = 0; u < 4; u++) {
                int idx = u * 256 + tid;
                int r = idx >> 3, c = idx & 7;
                uint32_t bo = (uint32_t)(r * 128 + c * 16);
                cp_async16(sbase + toff[t] + SW128(bo),
                           srcs[t] + (size_t)(row0[t] + r) * ND + k0 + c * 8);
            }
        }
    };

    load_stage(0);
    CP_COMMIT();

    for (int kc = 0; kc < 16; kc++) {
        if (kc < 15) {
            load_stage(kc + 1);
            CP_COMMIT();
            CP_WAIT1();
        } else {
            CP_WAIT0();
        }
        __syncthreads();

        const uint32_t stage = sb + (uint32_t)((kc & 1) * GSTAGE);
#pragma unroll
        for (int ks = 0; ks < 4; ks++) {
            uint32_t ah[2][4], al[2][4];
#pragma unroll
            for (int mi = 0; mi < 2; mi++) {
                uint32_t bo = (aRow + mi * 16) * 128 + (uint32_t)(ks * 32) + aKb;
                uint32_t off = SW128(bo);
                ldm_x4(ah[mi][0], ah[mi][1], ah[mi][2], ah[mi][3], stage + GOFF_AHI + off);
                ldm_x4(al[mi][0], al[mi][1], al[mi][2], al[mi][3], stage + GOFF_ALO + off);
            }
            uint32_t bh[4][4], bl[4][4];
#pragma unroll
            for (int nj = 0; nj < 4; nj++) {
                uint32_t bo = (bRow + nj * 16) * 128 + (uint32_t)(ks * 32) + bKb;
                uint32_t off = SW128(bo);
                ldm_x4(bh[nj][0], bh[nj][1], bh[nj][2], bh[nj][3], stage + GOFF_WHI + off);
                ldm_x4(bl[nj][0], bl[nj][1], bl[nj][2], bl[nj][3], stage + GOFF_WLO + off);
            }
#pragma unroll
            for (int mi = 0; mi < 2; mi++)
#pragma unroll
                for (int nj = 0; nj < 4; nj++) {
                    mma16816(acc[mi][nj * 2 + 0], ah[mi], &bh[nj][0]);
                    mma16816(acc[mi][nj * 2 + 0], ah[mi], &bl[nj][0]);
                    mma16816(acc[mi][nj * 2 + 0], al[mi], &bh[nj][0]);
                    mma16816(acc[mi][nj * 2 + 1], ah[mi], &bh[nj][2]);
                    mma16816(acc[mi][nj * 2 + 1], ah[mi], &bl[nj][2]);
                    mma16816(acc[mi][nj * 2 + 1], al[mi], &bh[nj][2]);
                }
        }
        __syncthreads();
    }

    // Epilogue
    __nv_bfloat16 *dHi = nullptr, *dLo = nullptr;
    if (mode == 1) { dHi = g_Qhi; dLo = g_Qlo; }
    else if (mode == 2) { dHi = g_Khi; dLo = g_Klo; }
    else if (mode == 3) { dHi = g_Vhi; dLo = g_Vlo; }

    const int g = lane >> 2, tg = lane & 3;
#pragma unroll
    for (int mi = 0; mi < 2; mi++) {
#pragma unroll
        for (int nj = 0; nj < 8; nj++) {
            int n = bn + wn * 64 + nj * 8 + tg * 2;
            float bx = bias[n], by = bias[n + 1];
            int m0 = bm + wm * 32 + mi * 16 + g;
#pragma unroll
            for (int half = 0; half < 2; half++) {
                int m = m0 + half * 8;
                float ox = acc[mi][nj][half * 2 + 0] + bx;
                float oy = acc[mi][nj][half * 2 + 1] + by;
                if (mode == 0) {
                    *(float2*)(Cp + (size_t)m * ND + n) = make_float2(ox, oy);
                } else {
                    int bb = m >> 11, ss = m & 2047;
                    int h = n >> 6, dd = n & 63;
                    size_t idx = (((size_t)(bb * NH + h) * NS + ss) * NDK) + dd;
                    uint32_t hi, lo;
                    split_pair(ox, oy, hi, lo);
                    *(uint32_t*)(dHi + idx) = hi;
                    *(uint32_t*)(dLo + idx) = lo;
                }
            }
        }
    }
}

// ---------------------------------------------------------------------------
// Flash attention on tensor cores (split bf16, 3-MMA for QK^T and P*V).
// One CTA = (b, h, 128-q-row tile); 8 warps, each owns an m16 slice.
// KV processed in 64-col tiles; double-buffered cp.async.
// Smem: Qhi/Qlo [128][64] (32KB, resident) + 2 stages x {Khi,Klo,Vhi,Vlo}
//       [64][64] (32KB/stage) = 96KB dynamic.
// P fragments built in registers from QK C-fragments (FA2 layout identity);
// V consumed via ldmatrix.trans. Output written as split bf16 to g_Ahi/g_Alo.
// ---------------------------------------------------------------------------
#define FQHI 0
#define FQLO 16384
#define FSTG 32768
#define FKHI 0
#define FKLO 8192
#define FVHI 16384
#define FVLO 24576
#define FLASH_SMEM (32768 + 2 * 32768)   // 98304

__global__ __launch_bounds__(256) void flash_mma(void)
{
    extern __shared__ __align__(1024) char fsm[];
    const uint32_t sb = smem_u32(fsm);
    const int tid = threadIdx.x;
    const int wid = tid >> 5;
    const int lane = tid & 31;
    const int g = lane >> 2, tg = lane & 3;
    const int qt = blockIdx.x, h = blockIdx.y, b = blockIdx.z;

    const size_t kvbase = (size_t)(b * NH + h) * NS * NDK;
    const size_t qbase  = kvbase + (size_t)qt * 128 * NDK;

    auto load_kv = [&](int kt) {
        uint32_t sbase = sb + FSTG + (uint32_t)((kt & 1) * 32768);
#pragma unroll
        for (int u = 0; u < 2; u++) {
            int idx = u * 256 + tid;
            int r = idx >> 3, c = idx & 7;
            uint32_t bo = SW128((uint32_t)(r * 128 + c * 16));
            size_t go = kvbase + (size_t)(kt * 64 + r) * NDK + c * 8;
            cp_async16(sbase + FKHI + bo, g_Khi + go);
            cp_async16(sbase + FKLO + bo, g_Klo + go);
            cp_async16(sbase + FVHI + bo, g_Vhi + go);
            cp_async16(sbase + FVLO + bo, g_Vlo + go);
        }
    };

    // Q tile (resident) + first KV stage
#pragma unroll
    for (int u = 0; u < 4; u++) {
        int idx = u * 256 + tid;
        int r = idx >> 3, c = idx & 7;
        uint32_t bo = SW128((uint32_t)(r * 128 + c * 16));
        size_t go = qbase + (size_t)r * NDK + c * 8;
        cp_async16(sb + FQHI + bo, g_Qhi + go);
        cp_async16(sb + FQLO + bo, g_Qlo + go);
    }
    load_kv(0);
    CP_COMMIT();

    // fragment address components
    const uint32_t aRow = (uint32_t)(wid * 16 + (lane & 15));
    const uint32_t aKb  = (uint32_t)((lane >> 4) << 4);
    const uint32_t bRow = (uint32_t)((lane & 7) + ((lane >> 4) & 1) * 8);
    const uint32_t bKb  = (uint32_t)(((lane >> 3) & 1) << 4);
    const uint32_t vRow = (uint32_t)((lane & 7) + ((lane >> 3) & 1) * 8);   // trans
    const uint32_t vNb  = (uint32_t)(((lane >> 4) & 1) << 4);

    uint32_t qh[4][4], ql[4][4];
    float o[8][4];
#pragma unroll
    for (int nj = 0; nj < 8; nj++)
#pragma unroll
        for (int t = 0; t < 4; t++) o[nj][t] = 0.f;

    const float NEG = __int_as_float(0xff800000);
    float m0 = NEG, m1 = NEG, l0 = 0.f, l1 = 0.f;
    const int qg0 = qt * 128 + wid * 16 + g;   // row g; row g+8 = qg0+8

    for (int kt = 0; kt < NS / 64; kt++) {
        if (kt < NS / 64 - 1) { load_kv(kt + 1); CP_COMMIT(); CP_WAIT1(); }
        else CP_WAIT0();
        __syncthreads();

        if (kt == 0) {
#pragma unroll
            for (int kk = 0; kk < 4; kk++) {
                uint32_t bo = SW128(aRow * 128 + (uint32_t)(kk * 32) + aKb);
                ldm_x4(qh[kk][0], qh[kk][1], qh[kk][2], qh[kk][3], sb + FQHI + bo);
                ldm_x4(ql[kk][0], ql[kk][1], ql[kk][2], ql[kk][3], sb + FQLO + bo);
            }
        }

        const uint32_t st = sb + FSTG + (uint32_t)((kt & 1) * 32768);

        // QK^T: sc[nj 0..7][4]
        float sc[8][4];
#pragma unroll
        for (int nj = 0; nj < 8; nj++)
#pragma unroll
            for (int t = 0; t < 4; t++) sc[nj][t] = 0.f;

#pragma unroll
        for (int kk = 0; kk < 4; kk++) {
#pragma unroll
            for (int njp = 0; njp < 4; njp++) {
                uint32_t bo = SW128((bRow + njp * 16) * 128 + (uint32_t)(kk * 32) + bKb);
                uint32_t bh4[4], bl4[4];
                ldm_x4(bh4[0], bh4[1], bh4[2], bh4[3], st + FKHI + bo);
                ldm_x4(bl4[0], bl4[1], bl4[2], bl4[3], st + FKLO + bo);
                mma16816(sc[2 * njp + 0], qh[kk], &bh4[0]);
                mma16816(sc[2 * njp + 0], ql[kk], &bh4[0]);
                mma16816(sc[2 * njp + 0], qh[kk], &bl4[0]);
                mma16816(sc[2 * njp + 1], qh[kk], &bh4[2]);
                mma16816(sc[2 * njp + 1], ql[kk], &bh4[2]);
                mma16816(sc[2 * njp + 1], qh[kk], &bl4[2]);
            }
        }

        // mask (bitmap) + scale + online softmax
        uint2 w0 = *(const uint2*)(g_maskbits + (size_t)qg0 * 32 + kt);
        uint2 w1 = *(const uint2*)(g_maskbits + (size_t)(qg0 + 8) * 32 + kt);
        float rmax0 = NEG, rmax1 = NEG;
#pragma unroll
        for (int nj = 0; nj < 8; nj++) {
            unsigned s0 = (nj < 4) ? w0.x : w0.y;
            unsigned s1 = (nj < 4) ? w1.x : w1.y;
            int sh = ((nj & 3) << 3) + (tg << 1);
            unsigned b0 = s0 >> sh, b1 = s1 >> sh;
            sc[nj][0] = (b0 & 1) ? sc[nj][0] * 0.125f : -1e9f;
            sc[nj][1] = (b0 & 2) ? sc[nj][1] * 0.125f : -1e9f;
            sc[nj][2] = (b1 & 1) ? sc[nj][2] * 0.125f : -1e9f;
            sc[nj][3] = (b1 & 2) ? sc[nj][3] * 0.125f : -1e9f;
            rmax0 = fmaxf(rmax0, fmaxf(sc[nj][0], sc[nj][1]));
            rmax1 = fmaxf(rmax1, fmaxf(sc[nj][2], sc[nj][3]));
        }
        rmax0 = fmaxf(rmax0, __shfl_xor_sync(0xffffffffu, rmax0, 1));
        rmax0 = fmaxf(rmax0, __shfl_xor_sync(0xffffffffu, rmax0, 2));
        rmax1 = fmaxf(rmax1, __shfl_xor_sync(0xffffffffu, rmax1, 1));
        rmax1 = fmaxf(rmax1, __shfl_xor_sync(0xffffffffu, rmax1, 2));

        float mn0 = fmaxf(m0, rmax0), mn1 = fmaxf(m1, rmax1);
        float corr0 = __expf(m0 - mn0), corr1 = __expf(m1 - mn1);
        float rs0 = 0.f, rs1 = 0.f;
#pragma unroll
        for (int nj = 0; nj < 8; nj++) {
            sc[nj][0] = __expf(sc[nj][0] - mn0);
            sc[nj][1] = __expf(sc[nj][1] - mn0);
            sc[nj][2] = __expf(sc[nj][2] - mn1);
            sc[nj][3] = __expf(sc[nj][3] - mn1);
            rs0 += sc[nj][0] + sc[nj][1];
            rs1 += sc[nj][2] + sc[nj][3];
        }
        rs0 += __shfl_xor_sync(0xffffffffu, rs0, 1);
        rs0 += __shfl_xor_sync(0xffffffffu, rs0, 2);
        rs1 += __shfl_xor_sync(0xffffffffu, rs1, 1);
        rs1 += __shfl_xor_sync(0xffffffffu, rs1, 2);

        l0 = l0 * corr0 + rs0;
        l1 = l1 * corr1 + rs1;
        m0 = mn0; m1 = mn1;
#pragma unroll
        for (int nj = 0; nj < 8; nj++) {
            o[nj][0] *= corr0; o[nj][1] *= corr0;
            o[nj][2] *= corr1; o[nj][3] *= corr1;
        }

        // P*V: build P fragments from sc (C->A layout identity), V via ldm.trans
#pragma unroll
        for (int kk = 0; kk < 4; kk++) {
            uint32_t ph[4], pl[4];
            split_pair(sc[2 * kk][0],     sc[2 * kk][1],     ph[0], pl[0]);
            split_pair(sc[2 * kk][2],     sc[2 * kk][3],     ph[1], pl[1]);
            split_pair(sc[2 * kk + 1][0], sc[2 * kk + 1][1], ph[2], pl[2]);
            split_pair(sc[2 * kk + 1][2], sc[2 * kk + 1][3], ph[3], pl[3]);
#pragma unroll
            for (int njp = 0; njp < 4; njp++) {
                uint32_t bo = SW128((uint32_t)(kk * 16 + vRow) * 128 +
                                    (uint32_t)(njp * 32) + vNb);
                uint32_t vh4[4], vl4[4];
                ldm_x4t(vh4[0], vh4[1], vh4[2], vh4[3], st + FVHI + bo);
                ldm_x4t(vl4[0], vl4[1], vl4[2], vl4[3], st + FVLO + bo);
                mma16816(o[2 * njp + 0], ph, &vh4[0]);
                mma16816(o[2 * njp + 0], pl, &vh4[0]);
                mma16816(o[2 * njp + 0], ph, &vl4[0]);
                mma16816(o[2 * njp + 1], ph, &vh4[2]);
                mma16816(o[2 * njp + 1], pl, &vh4[2]);
                mma16816(o[2 * njp + 1], ph, &vl4[2]);
            }
        }
        __syncthreads();
    }

    // epilogue: write split bf16 attention output into activation buffers
    float inv0 = 1.f / l0, inv1 = 1.f / l1;
    const size_t row0 = (size_t)(b * NS + qg0) * ND;
    const size_t row1 = row0 + (size_t)8 * ND;
#pragma unroll
    for (int njd = 0; njd < 8; njd++) {
        int col = h * NDK + njd * 8 + tg * 2;
        uint32_t hi, lo;
        split_pair(o[njd][0] * inv0, o[njd][1] * inv0, hi, lo);
        *(uint32_t*)(g_Ahi + row0 + col) = hi;
        *(uint32_t*)(g_Alo + row0 + col) = lo;
        split_pair(o[njd][2] * inv1, o[njd][3] * inv1, hi, lo);
        *(uint32_t*)(g_Ahi + row1 + col) = hi;
        *(uint32_t*)(g_Alo + row1 + col) = lo;
    }
}

// ---------------------------------------------------------------------------
extern "C" void kernel_launch(void* const* d_in, const int* in_sizes, int n_in,
                              void* d_out, int out_size)
{
    const float* q    = (const float*)d_in[0];
    const float* k    = (const float*)d_in[1];
    const float* v    = (const float*)d_in[2];
    const int*   mask = (const int*)d_in[3];
    const float* w_q  = (const float*)d_in[4];
    const float* b_q  = (const float*)d_in[5];
    const float* w_k  = (const float*)d_in[6];
    const float* b_k  = (const float*)d_in[7];
    const float* w_v  = (const float*)d_in[8];
    const float* b_v  = (const float*)d_in[9];
    const float* w_o  = (const float*)d_in[10];
    const float* b_o  = (const float*)d_in[11];

    cudaFuncSetAttribute(gemm_tc, cudaFuncAttributeMaxDynamicSharedMemorySize, GEMM_SMEM);
    cudaFuncSetAttribute(flash_mma, cudaFuncAttributeMaxDynamicSharedMemorySize, FLASH_SMEM);

    const int actBlocks = NM * ND / (4 * 256);  // 8192
    const int wBlocks   = ND * ND / (4 * 256);  // 1024
    dim3 ggrid(ND / 128, NM / 128);             // (8, 64)

    mask_pack<<<NS * NS / 64 / 256, 256>>>(mask);

    // Q projection
    split_wgt<<<wBlocks, 256>>>(w_q);
    split_act<<<actBlocks, 256>>>(q);
    gemm_tc<<<ggrid, 256, GEMM_SMEM>>>(b_q, nullptr, 1);
    // K projection
    split_wgt<<<wBlocks, 256>>>(w_k);
    split_act<<<actBlocks, 256>>>(k);
    gemm_tc<<<ggrid, 256, GEMM_SMEM>>>(b_k, nullptr, 2);
    // V projection
    split_wgt<<<wBlocks, 256>>>(w_v);
    split_act<<<actBlocks, 256>>>(v);
    gemm_tc<<<ggrid, 256, GEMM_SMEM>>>(b_v, nullptr, 3);

    // attention (writes split bf16 output directly into g_Ahi/g_Alo)
    dim3 agrid(NS / 128, NH, NB);  // (16, 16, 4)
    flash_mma<<<agrid, 256, FLASH_SMEM>>>();

    // output projection
    split_wgt<<<wBlocks, 256>>>(w_o);
    gemm_tc<<<ggrid, 256, GEMM_SMEM>>>(b_o, (float*)d_out, 0);
}

// round 6
// speedup vs baseline: 4.8327x; 1.0686x over previous
#include <cuda_runtime.h>
#include <cuda_bf16.h>
#include <cstdint>

typedef unsigned long long u64;

// Problem constants
#define NB 4
#define NS 2048
#define ND 1024
#define NH 16
#define NDK 64
#define NM (NB * NS)   // 8192 rows

// ---------------------------------------------------------------------------
// Scratch (device globals: allocation-free)
// g_Ahi/g_Alo: 3 activation slots (q,k,v); slot 0 reused for attention output.
// g_Whi/g_Wlo: 4 weight slots (q,k,v,o).
// ---------------------------------------------------------------------------
__device__ __align__(16) __nv_bfloat16 g_Ahi[3 * NM * ND];
__device__ __align__(16) __nv_bfloat16 g_Alo[3 * NM * ND];
__device__ __align__(16) __nv_bfloat16 g_Whi[4 * ND * ND];
__device__ __align__(16) __nv_bfloat16 g_Wlo[4 * ND * ND];
__device__ __align__(16) __nv_bfloat16 g_Qhi[NB * NH * NS * NDK];  // [B,H,S,dk]
__device__ __align__(16) __nv_bfloat16 g_Qlo[NB * NH * NS * NDK];
__device__ __align__(16) __nv_bfloat16 g_Khi[NB * NH * NS * NDK];
__device__ __align__(16) __nv_bfloat16 g_Klo[NB * NH * NS * NDK];
__device__ __align__(16) __nv_bfloat16 g_Vhi[NB * NH * NS * NDK];
__device__ __align__(16) __nv_bfloat16 g_Vlo[NB * NH * NS * NDK];
__device__ __align__(16) u64 g_maskbits[NS * NS / 64];    // bit-packed mask

// ---------------------------------------------------------------------------
// Helpers
// ---------------------------------------------------------------------------
__device__ __forceinline__ uint32_t smem_u32(const void* p) {
    uint32_t a;
    asm("{ .reg .u64 t; cvta.to.shared.u64 t, %1; cvt.u32.u64 %0, t; }" : "=r"(a) : "l"(p));
    return a;
}
#define SW128(bo) ((bo) ^ (((bo) >> 3) & 0x70))

__device__ __forceinline__ void ldm_x4(uint32_t& r0, uint32_t& r1, uint32_t& r2,
                                       uint32_t& r3, uint32_t addr) {
    asm volatile("ldmatrix.sync.aligned.m8n8.x4.shared.b16 {%0,%1,%2,%3}, [%4];"
                 : "=r"(r0), "=r"(r1), "=r"(r2), "=r"(r3) : "r"(addr));
}
__device__ __forceinline__ void ldm_x4t(uint32_t& r0, uint32_t& r1, uint32_t& r2,
                                        uint32_t& r3, uint32_t addr) {
    asm volatile("ldmatrix.sync.aligned.m8n8.x4.trans.shared.b16 {%0,%1,%2,%3}, [%4];"
                 : "=r"(r0), "=r"(r1), "=r"(r2), "=r"(r3) : "r"(addr));
}
__device__ __forceinline__ void mma16816(float* d, const uint32_t* a, const uint32_t* b) {
    asm volatile("mma.sync.aligned.m16n8k16.row.col.f32.bf16.bf16.f32 "
                 "{%0,%1,%2,%3}, {%4,%5,%6,%7}, {%8,%9}, {%0,%1,%2,%3};"
                 : "+f"(d[0]), "+f"(d[1]), "+f"(d[2]), "+f"(d[3])
                 : "r"(a[0]), "r"(a[1]), "r"(a[2]), "r"(a[3]), "r"(b[0]), "r"(b[1]));
}

__device__ __forceinline__ void cp_async16(uint32_t s, const void* g) {
    asm volatile("{ .reg .u64 gg; cvta.to.global.u64 gg, %1; "
                 "cp.async.cg.shared.global [%0], [gg], 16; }"
                 :: "r"(s), "l"(g) : "memory");
}
#define CP_COMMIT() asm volatile("cp.async.commit_group;" ::: "memory")
#define CP_WAIT1()  asm volatile("cp.async.wait_group 1;" ::: "memory")
#define CP_WAIT0()  asm volatile("cp.async.wait_group 0;" ::: "memory")

// split fp32 pair -> packed bf16 hi pair + bf16 residual pair
__device__ __forceinline__ void split_pair(float a, float b, uint32_t& hi, uint32_t& lo) {
    __nv_bfloat16 ha = __float2bfloat16(a), hb = __float2bfloat16(b);
    __nv_bfloat16 la = __float2bfloat16(a - __bfloat162float(ha));
    __nv_bfloat16 lb = __float2bfloat16(b - __bfloat162float(hb));
    __nv_bfloat162 H(ha, hb), L(la, lb);
    hi = *reinterpret_cast<uint32_t*>(&H);
    lo = *reinterpret_cast<uint32_t*>(&L);
}

// ---------------------------------------------------------------------------
// Preprocess kernels
// ---------------------------------------------------------------------------
__global__ __launch_bounds__(256) void split_act(const float* __restrict__ src, int slot)
{
    size_t base = (size_t)slot * NM * ND;
    int i = (blockIdx.x * 256 + threadIdx.x) * 4;
    float4 v = *(const float4*)(src + i);
    uint32_t h0, l0, h1, l1;
    split_pair(v.x, v.y, h0, l0);
    split_pair(v.z, v.w, h1, l1);
    *(uint32_t*)(g_Ahi + base + i) = h0; *(uint32_t*)(g_Ahi + base + i + 2) = h1;
    *(uint32_t*)(g_Alo + base + i) = l0; *(uint32_t*)(g_Alo + base + i + 2) = l1;
}

__global__ __launch_bounds__(256) void split_wgt(const float* __restrict__ src, int slot)
{
    size_t base = (size_t)slot * ND * ND;
    int i = (blockIdx.x * 256 + threadIdx.x) * 4;
    float4 v = *(const float4*)(src + i);
    uint32_t h0, l0, h1, l1;
    split_pair(v.x, v.y, h0, l0);
    split_pair(v.z, v.w, h1, l1);
    *(uint32_t*)(g_Whi + base + i) = h0; *(uint32_t*)(g_Whi + base + i + 2) = h1;
    *(uint32_t*)(g_Wlo + base + i) = l0; *(uint32_t*)(g_Wlo + base + i + 2) = l1;
}

// mask int32[S][S] -> bitmap u64[S][S/64]
__global__ __launch_bounds__(256) void mask_pack(const int* __restrict__ mask)
{
    int w = blockIdx.x * 256 + threadIdx.x;     // 0 .. 65535
    const int4* src = (const int4*)(mask + (size_t)w * 64);
    u64 bits = 0;
#pragma unroll
    for (int q = 0; q < 16; q++) {
        int4 v = src[q];
        bits |= ((u64)(v.x != 0) << (q * 4 + 0)) | ((u64)(v.y != 0) << (q * 4 + 1))
              | ((u64)(v.z != 0) << (q * 4 + 2)) | ((u64)(v.w != 0) << (q * 4 + 3));
    }
    g_maskbits[w] = bits;
}

// ---------------------------------------------------------------------------
// mma.sync GEMM, 2-stage cp.async pipeline, 512 threads / 16 warps.
// Warp grid 4(m) x 4(n): warp tile 32x32, acc = 32 regs/thread.
// base_mode 1: QKV fused launch, grid.z=3 -> mode = 1 + z (split bf16 heads out).
// base_mode 0: output projection, fp32 row-major to Cp.
// ---------------------------------------------------------------------------
#define GOFF_AHI 0
#define GOFF_ALO 16384
#define GOFF_WHI 32768
#define GOFF_WLO 49152
#define GSTAGE   65536
#define GEMM_SMEM (2 * GSTAGE)

__global__ __launch_bounds__(512) void gemm_tc(
    const float* __restrict__ bias0, const float* __restrict__ bias1,
    const float* __restrict__ bias2, float* __restrict__ Cp, int base_mode)
{
    extern __shared__ __align__(1024) char smem[];
    const uint32_t sb = smem_u32(smem);
    const int tid = threadIdx.x;
    const int wid = tid >> 5;
    const int lane = tid & 31;
    const int wm = wid >> 2;        // 0..3
    const int wn = wid & 3;         // 0..3
    const int bm = blockIdx.y * 128;
    const int bn = blockIdx.x * 128;
    const int z = blockIdx.z;
    const int mode = (base_mode == 0) ? 0 : 1 + z;
    const float* bias = (z == 0) ? bias0 : (z == 1) ? bias1 : bias2;

    const int aslot = (mode == 0) ? 0 : mode - 1;
    const int wslot = (mode == 0) ? 3 : mode - 1;
    const __nv_bfloat16* Ahi = g_Ahi + (size_t)aslot * NM * ND;
    const __nv_bfloat16* Alo = g_Alo + (size_t)aslot * NM * ND;
    const __nv_bfloat16* Whi = g_Whi + (size_t)wslot * ND * ND;
    const __nv_bfloat16* Wlo = g_Wlo + (size_t)wslot * ND * ND;

    const __nv_bfloat16* srcs[4] = {Ahi, Alo, Whi, Wlo};
    const int row0[4] = {bm, bm, bn, bn};
    const uint32_t toff[4] = {GOFF_AHI, GOFF_ALO, GOFF_WHI, GOFF_WLO};

    float acc[2][4][4];
#pragma unroll
    for (int mi = 0; mi < 2; mi++)
#pragma unroll
        for (int c = 0; c < 4; c++)
#pragma unroll
            for (int t = 0; t < 4; t++) acc[mi][c][t] = 0.f;

    const uint32_t aRow = (uint32_t)(wm * 32 + (lane & 15));
    const uint32_t aKb  = (uint32_t)((lane >> 4) << 4);
    const uint32_t bRow = (uint32_t)(wn * 32 + (lane & 7) + ((lane >> 4) & 1) * 8);
    const uint32_t bKb  = (uint32_t)(((lane >> 3) & 1) << 4);

    auto load_stage = [&](int kc) {
        const int k0 = kc * 64;
        const uint32_t sbase = sb + (uint32_t)((kc & 1) * GSTAGE);
#pragma unroll
        for (int t = 0; t < 4; t++) {
#pragma unroll
            for (int u = 0; u < 2; u++) {
                int idx = u * 512 + tid;
                int r = idx >> 3, c = idx & 7;
                uint32_t bo = (uint32_t)(r * 128 + c * 16);
                cp_async16(sbase + toff[t] + SW128(bo),
                           srcs[t] + (size_t)(row0[t] + r) * ND + k0 + c * 8);
            }
        }
    };

    load_stage(0);
    CP_COMMIT();

    for (int kc = 0; kc < 16; kc++) {
        if (kc < 15) {
            load_stage(kc + 1);
            CP_COMMIT();
            CP_WAIT1();
        } else {
            CP_WAIT0();
        }
        __syncthreads();

        const uint32_t stage = sb + (uint32_t)((kc & 1) * GSTAGE);
#pragma unroll
        for (int ks = 0; ks < 4; ks++) {
            uint32_t ah[2][4], al[2][4];
#pragma unroll
            for (int mi = 0; mi < 2; mi++) {
                uint32_t off = SW128((aRow + mi * 16) * 128 + (uint32_t)(ks * 32) + aKb);
                ldm_x4(ah[mi][0], ah[mi][1], ah[mi][2], ah[mi][3], stage + GOFF_AHI + off);
                ldm_x4(al[mi][0], al[mi][1], al[mi][2], al[mi][3], stage + GOFF_ALO + off);
            }
            uint32_t bh[2][4], bl[2][4];
#pragma unroll
            for (int nj = 0; nj < 2; nj++) {
                uint32_t off = SW128((bRow + nj * 16) * 128 + (uint32_t)(ks * 32) + bKb);
                ldm_x4(bh[nj][0], bh[nj][1], bh[nj][2], bh[nj][3], stage + GOFF_WHI + off);
                ldm_x4(bl[nj][0], bl[nj][1], bl[nj][2], bl[nj][3], stage + GOFF_WLO + off);
            }
#pragma unroll
            for (int mi = 0; mi < 2; mi++)
#pragma unroll
                for (int nj = 0; nj < 2; nj++) {
                    mma16816(acc[mi][nj * 2 + 0], ah[mi], &bh[nj][0]);
                    mma16816(acc[mi][nj * 2 + 0], al[mi], &bh[nj][0]);
                    mma16816(acc[mi][nj * 2 + 0], ah[mi], &bl[nj][0]);
                    mma16816(acc[mi][nj * 2 + 1], ah[mi], &bh[nj][2]);
                    mma16816(acc[mi][nj * 2 + 1], al[mi], &bh[nj][2]);
                    mma16816(acc[mi][nj * 2 + 1], ah[mi], &bl[nj][2]);
                }
        }
        __syncthreads();
    }

    // Epilogue
    __nv_bfloat16 *dHi = nullptr, *dLo = nullptr;
    if (mode == 1) { dHi = g_Qhi; dLo = g_Qlo; }
    else if (mode == 2) { dHi = g_Khi; dLo = g_Klo; }
    else if (mode == 3) { dHi = g_Vhi; dLo = g_Vlo; }

    const int g = lane >> 2, tg = lane & 3;
#pragma unroll
    for (int mi = 0; mi < 2; mi++) {
#pragma unroll
        for (int c = 0; c < 4; c++) {
            int n = bn + wn * 32 + c * 8 + tg * 2;
            float bx = bias[n], by = bias[n + 1];
            int m0 = bm + wm * 32 + mi * 16 + g;
#pragma unroll
            for (int half = 0; half < 2; half++) {
                int m = m0 + half * 8;
                float ox = acc[mi][c][half * 2 + 0] + bx;
                float oy = acc[mi][c][half * 2 + 1] + by;
                if (mode == 0) {
                    *(float2*)(Cp + (size_t)m * ND + n) = make_float2(ox, oy);
                } else {
                    int bb = m >> 11, ss = m & 2047;
                    int h = n >> 6, dd = n & 63;
                    size_t idx = (((size_t)(bb * NH + h) * NS + ss) * NDK) + dd;
                    uint32_t hi, lo;
                    split_pair(ox, oy, hi, lo);
                    *(uint32_t*)(dHi + idx) = hi;
                    *(uint32_t*)(dLo + idx) = lo;
                }
            }
        }
    }
}

// ---------------------------------------------------------------------------
// Flash attention on tensor cores (split bf16, 3-MMA for QK^T and P*V).
// One CTA = (b, h, 128-q-row tile); 8 warps; launch_bounds(256,2) -> 2 CTAs/SM.
// Q fragments re-loaded from smem per tile (saves 32 regs for the 128-reg cap).
// ---------------------------------------------------------------------------
#define FQHI 0
#define FQLO 16384
#define FSTG 32768
#define FKHI 0
#define FKLO 8192
#define FVHI 16384
#define FVLO 24576
#define FLASH_SMEM (32768 + 2 * 32768)   // 98304

__global__ __launch_bounds__(256, 2) void flash_mma(void)
{
    extern __shared__ __align__(1024) char fsm[];
    const uint32_t sb = smem_u32(fsm);
    const int tid = threadIdx.x;
    const int wid = tid >> 5;
    const int lane = tid & 31;
    const int g = lane >> 2, tg = lane & 3;
    const int qt = blockIdx.x, h = blockIdx.y, b = blockIdx.z;

    const size_t kvbase = (size_t)(b * NH + h) * NS * NDK;
    const size_t qbase  = kvbase + (size_t)qt * 128 * NDK;

    auto load_kv = [&](int kt) {
        uint32_t sbase = sb + FSTG + (uint32_t)((kt & 1) * 32768);
#pragma unroll
        for (int u = 0; u < 2; u++) {
            int idx = u * 256 + tid;
            int r = idx >> 3, c = idx & 7;
            uint32_t bo = SW128((uint32_t)(r * 128 + c * 16));
            size_t go = kvbase + (size_t)(kt * 64 + r) * NDK + c * 8;
            cp_async16(sbase + FKHI + bo, g_Khi + go);
            cp_async16(sbase + FKLO + bo, g_Klo + go);
            cp_async16(sbase + FVHI + bo, g_Vhi + go);
            cp_async16(sbase + FVLO + bo, g_Vlo + go);
        }
    };

    // Q tile (resident) + first KV stage
#pragma unroll
    for (int u = 0; u < 4; u++) {
        int idx = u * 256 + tid;
        int r = idx >> 3, c = idx & 7;
        uint32_t bo = SW128((uint32_t)(r * 128 + c * 16));
        size_t go = qbase + (size_t)r * NDK + c * 8;
        cp_async16(sb + FQHI + bo, g_Qhi + go);
        cp_async16(sb + FQLO + bo, g_Qlo + go);
    }
    load_kv(0);
    CP_COMMIT();

    // fragment address components
    const uint32_t aRow = (uint32_t)(wid * 16 + (lane & 15));
    const uint32_t aKb  = (uint32_t)((lane >> 4) << 4);
    const uint32_t bRow = (uint32_t)((lane & 7) + ((lane >> 4) & 1) * 8);
    const uint32_t bKb  = (uint32_t)(((lane >> 3) & 1) << 4);
    const uint32_t vRow = (uint32_t)((lane & 7) + ((lane >> 3) & 1) * 8);   // trans
    const uint32_t vNb  = (uint32_t)(((lane >> 4) & 1) << 4);

    float o[8][4];
#pragma unroll
    for (int nj = 0; nj < 8; nj++)
#pragma unroll
        for (int t = 0; t < 4; t++) o[nj][t] = 0.f;

    const float NEG = __int_as_float(0xff800000);
    float m0 = NEG, m1 = NEG, l0 = 0.f, l1 = 0.f;
    const int qg0 = qt * 128 + wid * 16 + g;   // row g; row g+8 = qg0+8

    for (int kt = 0; kt < NS / 64; kt++) {
        if (kt < NS / 64 - 1) { load_kv(kt + 1); CP_COMMIT(); CP_WAIT1(); }
        else CP_WAIT0();
        __syncthreads();

        const uint32_t st = sb + FSTG + (uint32_t)((kt & 1) * 32768);

        // QK^T: sc[nj 0..7][4]
        float sc[8][4];
#pragma unroll
        for (int nj = 0; nj < 8; nj++)
#pragma unroll
            for (int t = 0; t < 4; t++) sc[nj][t] = 0.f;

#pragma unroll
        for (int kk = 0; kk < 4; kk++) {
            uint32_t qh4[4], ql4[4];
            uint32_t qo = SW128(aRow * 128 + (uint32_t)(kk * 32) + aKb);
            ldm_x4(qh4[0], qh4[1], qh4[2], qh4[3], sb + FQHI + qo);
            ldm_x4(ql4[0], ql4[1], ql4[2], ql4[3], sb + FQLO + qo);
#pragma unroll
            for (int njp = 0; njp < 4; njp++) {
                uint32_t bo = SW128((bRow + njp * 16) * 128 + (uint32_t)(kk * 32) + bKb);
                uint32_t bh4[4], bl4[4];
                ldm_x4(bh4[0], bh4[1], bh4[2], bh4[3], st + FKHI + bo);
                ldm_x4(bl4[0], bl4[1], bl4[2], bl4[3], st + FKLO + bo);
                mma16816(sc[2 * njp + 0], qh4, &bh4[0]);
                mma16816(sc[2 * njp + 0], ql4, &bh4[0]);
                mma16816(sc[2 * njp + 0], qh4, &bl4[0]);
                mma16816(sc[2 * njp + 1], qh4, &bh4[2]);
                mma16816(sc[2 * njp + 1], ql4, &bh4[2]);
                mma16816(sc[2 * njp + 1], qh4, &bl4[2]);
            }
        }

        // mask (bitmap) + scale + online softmax
        uint2 w0 = *(const uint2*)(g_maskbits + (size_t)qg0 * 32 + kt);
        uint2 w1 = *(const uint2*)(g_maskbits + (size_t)(qg0 + 8) * 32 + kt);
        float rmax0 = NEG, rmax1 = NEG;
#pragma unroll
        for (int nj = 0; nj < 8; nj++) {
            unsigned s0 = (nj < 4) ? w0.x : w0.y;
            unsigned s1 = (nj < 4) ? w1.x : w1.y;
            int sh = ((nj & 3) << 3) + (tg << 1);
            unsigned b0 = s0 >> sh, b1 = s1 >> sh;
            sc[nj][0] = (b0 & 1) ? sc[nj][0] * 0.125f : -1e9f;
            sc[nj][1] = (b0 & 2) ? sc[nj][1] * 0.125f : -1e9f;
            sc[nj][2] = (b1 & 1) ? sc[nj][2] * 0.125f : -1e9f;
            sc[nj][3] = (b1 & 2) ? sc[nj][3] * 0.125f : -1e9f;
            rmax0 = fmaxf(rmax0, fmaxf(sc[nj][0], sc[nj][1]));
            rmax1 = fmaxf(rmax1, fmaxf(sc[nj][2], sc[nj][3]));
        }
        rmax0 = fmaxf(rmax0, __shfl_xor_sync(0xffffffffu, rmax0, 1));
        rmax0 = fmaxf(rmax0, __shfl_xor_sync(0xffffffffu, rmax0, 2));
        rmax1 = fmaxf(rmax1, __shfl_xor_sync(0xffffffffu, rmax1, 1));
        rmax1 = fmaxf(rmax1, __shfl_xor_sync(0xffffffffu, rmax1, 2));

        float mn0 = fmaxf(m0, rmax0), mn1 = fmaxf(m1, rmax1);
        float corr0 = __expf(m0 - mn0), corr1 = __expf(m1 - mn1);
        float rs0 = 0.f, rs1 = 0.f;
#pragma unroll
        for (int nj = 0; nj < 8; nj++) {
            sc[nj][0] = __expf(sc[nj][0] - mn0);
            sc[nj][1] = __expf(sc[nj][1] - mn0);
            sc[nj][2] = __expf(sc[nj][2] - mn1);
            sc[nj][3] = __expf(sc[nj][3] - mn1);
            rs0 += sc[nj][0] + sc[nj][1];
            rs1 += sc[nj][2] + sc[nj][3];
        }
        rs0 += __shfl_xor_sync(0xffffffffu, rs0, 1);
        rs0 += __shfl_xor_sync(0xffffffffu, rs0, 2);
        rs1 += __shfl_xor_sync(0xffffffffu, rs1, 1);
        rs1 += __shfl_xor_sync(0xffffffffu, rs1, 2);

        l0 = l0 * corr0 + rs0;
        l1 = l1 * corr1 + rs1;
        m0 = mn0; m1 = mn1;
#pragma unroll
        for (int nj = 0; nj < 8; nj++) {
            o[nj][0] *= corr0; o[nj][1] *= corr0;
            o[nj][2] *= corr1; o[nj][3] *= corr1;
        }

        // P*V: build P fragments from sc (C->A layout identity), V via ldm.trans
#pragma unroll
        for (int kk = 0; kk < 4; kk++) {
            uint32_t ph[4], pl[4];
            split_pair(sc[2 * kk][0],     sc[2 * kk][1],     ph[0], pl[0]);
            split_pair(sc[2 * kk][2],     sc[2 * kk][3],     ph[1], pl[1]);
            split_pair(sc[2 * kk + 1][0], sc[2 * kk + 1][1], ph[2], pl[2]);
            split_pair(sc[2 * kk + 1][2], sc[2 * kk + 1][3], ph[3], pl[3]);
#pragma unroll
            for (int njp = 0; njp < 4; njp++) {
                uint32_t bo = SW128((uint32_t)(kk * 16 + vRow) * 128 +
                                    (uint32_t)(njp * 32) + vNb);
                uint32_t vh4[4], vl4[4];
                ldm_x4t(vh4[0], vh4[1], vh4[2], vh4[3], st + FVHI + bo);
                ldm_x4t(vl4[0], vl4[1], vl4[2], vl4[3], st + FVLO + bo);
                mma16816(o[2 * njp + 0], ph, &vh4[0]);
                mma16816(o[2 * njp + 0], pl, &vh4[0]);
                mma16816(o[2 * njp + 0], ph, &vl4[0]);
                mma16816(o[2 * njp + 1], ph, &vh4[2]);
                mma16816(o[2 * njp + 1], pl, &vh4[2]);
                mma16816(o[2 * njp + 1], ph, &vl4[2]);
            }
        }
        __syncthreads();
    }

    // epilogue: write split bf16 attention output into activation slot 0
    float inv0 = 1.f / l0, inv1 = 1.f / l1;
    const size_t row0 = (size_t)(b * NS + qg0) * ND;
    const size_t row1 = row0 + (size_t)8 * ND;
#pragma unroll
    for (int njd = 0; njd < 8; njd++) {
        int col = h * NDK + njd * 8 + tg * 2;
        uint32_t hi, lo;
        split_pair(o[njd][0] * inv0, o[njd][1] * inv0, hi, lo);
        *(uint32_t*)(g_Ahi + row0 + col) = hi;
        *(uint32_t*)(g_Alo + row0 + col) = lo;
        split_pair(o[njd][2] * inv1, o[njd][3] * inv1, hi, lo);
        *(uint32_t*)(g_Ahi + row1 + col) = hi;
        *(uint32_t*)(g_Alo + row1 + col) = lo;
    }
}

// ---------------------------------------------------------------------------
extern "C" void kernel_launch(void* const* d_in, const int* in_sizes, int n_in,
                              void* d_out, int out_size)
{
    const float* q    = (const float*)d_in[0];
    const float* k    = (const float*)d_in[1];
    const float* v    = (const float*)d_in[2];
    const int*   mask = (const int*)d_in[3];
    const float* w_q  = (const float*)d_in[4];
    const float* b_q  = (const float*)d_in[5];
    const float* w_k  = (const float*)d_in[6];
    const float* b_k  = (const float*)d_in[7];
    const float* w_v  = (const float*)d_in[8];
    const float* b_v  = (const float*)d_in[9];
    const float* w_o  = (const float*)d_in[10];
    const float* b_o  = (const float*)d_in[11];

    cudaFuncSetAttribute(gemm_tc, cudaFuncAttributeMaxDynamicSharedMemorySize, GEMM_SMEM);
    cudaFuncSetAttribute(flash_mma, cudaFuncAttributeMaxDynamicSharedMemorySize, FLASH_SMEM);

    const int actBlocks = NM * ND / (4 * 256);  // 8192
    const int wBlocks   = ND * ND / (4 * 256);  // 1024

    mask_pack<<<NS * NS / 64 / 256, 256>>>(mask);

    // weight + activation splits
    split_wgt<<<wBlocks, 256>>>(w_q, 0);
    split_wgt<<<wBlocks, 256>>>(w_k, 1);
    split_wgt<<<wBlocks, 256>>>(w_v, 2);
    split_wgt<<<wBlocks, 256>>>(w_o, 3);
    split_act<<<actBlocks, 256>>>(q, 0);
    split_act<<<actBlocks, 256>>>(k, 1);
    split_act<<<actBlocks, 256>>>(v, 2);

    // fused QKV projections (one launch, better wave packing)
    dim3 qkvgrid(ND / 128, NM / 128, 3);        // (8, 64, 3)
    gemm_tc<<<qkvgrid, 512, GEMM_SMEM>>>(b_q, b_k, b_v, nullptr, 1);

    // attention (writes split bf16 output into activation slot 0)
    dim3 agrid(NS / 128, NH, NB);               // (16, 16, 4)
    flash_mma<<<agrid, 256, FLASH_SMEM>>>();

    // output projection
    dim3 ogrid(ND / 128, NM / 128, 1);          // (8, 64)
    gemm_tc<<<ogrid, 512, GEMM_SMEM>>>(b_o, b_o, b_o, (float*)d_out, 0);
}